// round 5
// baseline (speedup 1.0000x reference)
#include <cuda_runtime.h>
#include <cuda_bf16.h>
#include <stdint.h>
#include <math.h>

#define S_LEN   2048
#define D_MODEL 1024
#define NHEADS  16
#define DKH     64
#define HALF_WIN 128
#define BQ      64
#define BKC     64
#define BATCH   2
#define MROWS   (BATCH * S_LEN)   // 4096
#define K3      (3 * D_MODEL)     // 3072
#define NQKV    3072
#define APAD    68                 // floats per smem row in attention tiles

// ---------------- scratch (static device globals; no allocation) -----------
__device__ float g_qkv[MROWS * NQKV];                // fused q|k|v fp32
__device__ __nv_bfloat16 g_xa  [MROWS * K3];         // x split [hi|lo|hi]
__device__ __nv_bfloat16 g_aoa [MROWS * K3];         // attn-out split (written by attn)
__device__ __nv_bfloat16 g_wqkv[NQKV * K3];          // [Wq;Wk;Wv] split [hi|hi|lo]
__device__ __nv_bfloat16 g_wo  [D_MODEL * K3];       // Wo split

// ---------------- fp32 -> bf16x3 split conversion ---------------------------
__global__ __launch_bounds__(256) void conv_split(
    const float* __restrict__ in, __nv_bfloat16* __restrict__ out, int modeB)
{
    int r = blockIdx.x;
    int c = threadIdx.x * 4;
    float4 v = *(const float4*)(in + (size_t)r * D_MODEL + c);
    float f[4] = {v.x, v.y, v.z, v.w};
    __nv_bfloat16 hi[4], lo[4];
    #pragma unroll
    for (int j = 0; j < 4; j++) {
        hi[j] = __float2bfloat16(f[j]);
        lo[j] = __float2bfloat16(f[j] - __bfloat162float(hi[j]));
    }
    __nv_bfloat162 hp0 = __halves2bfloat162(hi[0], hi[1]);
    __nv_bfloat162 hp1 = __halves2bfloat162(hi[2], hi[3]);
    __nv_bfloat162 lp0 = __halves2bfloat162(lo[0], lo[1]);
    __nv_bfloat162 lp1 = __halves2bfloat162(lo[2], lo[3]);
    __nv_bfloat162* o0 = (__nv_bfloat162*)(out + (size_t)r * K3 + c);
    __nv_bfloat162* o1 = (__nv_bfloat162*)(out + (size_t)r * K3 + D_MODEL + c);
    __nv_bfloat162* o2 = (__nv_bfloat162*)(out + (size_t)r * K3 + 2 * D_MODEL + c);
    o0[0] = hp0; o0[1] = hp1;
    if (modeB) { o1[0] = hp0; o1[1] = hp1; o2[0] = lp0; o2[1] = lp1; }
    else       { o1[0] = lp0; o1[1] = lp1; o2[0] = hp0; o2[1] = hp1; }
}

// ---------------- mma.sync bf16 GEMM: Y[M,N] = A[M,K3] @ B[N,K3]^T ----------
#define GBM 128
#define GBN 128
#define GBK 32
#define PADK 40
#define STG 4
#define SMEM_GEMM (STG * (GBM + GBN) * PADK * 2)   // 81920 B

__device__ __forceinline__ uint32_t s2u(const void* p) {
    uint32_t a;
    asm("{ .reg .u64 t; cvta.to.shared.u64 t, %1; cvt.u32.u64 %0, t; }"
        : "=r"(a) : "l"(p));
    return a;
}
__device__ __forceinline__ void cp16(uint32_t dst, const void* src) {
    asm volatile("cp.async.cg.shared.global [%0], [%1], 16;" :: "r"(dst), "l"(src));
}
__device__ __forceinline__ void ldmx4(uint32_t& r0, uint32_t& r1, uint32_t& r2,
                                      uint32_t& r3, uint32_t addr) {
    asm volatile("ldmatrix.sync.aligned.m8n8.x4.shared.b16 {%0,%1,%2,%3}, [%4];"
                 : "=r"(r0), "=r"(r1), "=r"(r2), "=r"(r3) : "r"(addr));
}

__global__ __launch_bounds__(256, 2) void gemm_mma(
    const __nv_bfloat16* __restrict__ A,
    const __nv_bfloat16* __restrict__ B,
    float* __restrict__ Y, int N)
{
    extern __shared__ __nv_bfloat16 smem_g[];

    int tid = threadIdx.x;
    int wid = tid >> 5, lane = tid & 31;
    int wm = wid & 1, wn = wid >> 1;
    int bm = blockIdx.y * GBM, bn = blockIdx.x * GBN;
    int g = lane >> 2, tig = lane & 3;

    int lrow = tid >> 2;
    int lch  = tid & 3;

    uint32_t as_base = s2u(smem_g);
    uint32_t bs_base = as_base + STG * GBM * PADK * 2;

    uint32_t a_ld = as_base +
        ((uint32_t)(wm * 64 + (lane & 15)) * PADK + ((lane >> 4) * 8)) * 2;
    uint32_t b_ld = bs_base +
        ((uint32_t)(wn * 32 + ((lane >> 4) * 8) + (lane & 7)) * PADK +
         (((lane >> 3) & 1) * 8)) * 2;

    const int NIT = K3 / GBK;                   // 96
    const uint32_t ASTG = GBM * PADK * 2;
    const uint32_t BSTG = GBN * PADK * 2;

#define LOAD_STAGE(s, k0)                                                     \
    do {                                                                      \
        _Pragma("unroll")                                                     \
        for (int i = 0; i < 2; i++) {                                         \
            int row = lrow + i * 64;                                          \
            cp16(as_base + (uint32_t)(s) * ASTG + (row * PADK + lch * 8) * 2, \
                 A + (size_t)(bm + row) * K3 + (k0) + lch * 8);               \
            cp16(bs_base + (uint32_t)(s) * BSTG + (row * PADK + lch * 8) * 2, \
                 B + (size_t)(bn + row) * K3 + (k0) + lch * 8);               \
        }                                                                     \
    } while (0)

    LOAD_STAGE(0, 0);
    asm volatile("cp.async.commit_group;");
    LOAD_STAGE(1, GBK);
    asm volatile("cp.async.commit_group;");
    LOAD_STAGE(2, 2 * GBK);
    asm volatile("cp.async.commit_group;");

    float acc[4][4][4];
    #pragma unroll
    for (int i = 0; i < 4; i++)
        #pragma unroll
        for (int j = 0; j < 4; j++)
            #pragma unroll
            for (int t = 0; t < 4; t++) acc[i][j][t] = 0.f;

    for (int it = 0; it < NIT; it++) {
        int s = it & (STG - 1);
        asm volatile("cp.async.wait_group 2;");
        __syncthreads();

        uint32_t a_s = a_ld + s * ASTG;
        uint32_t b_s = b_ld + s * BSTG;

        #pragma unroll
        for (int kk = 0; kk < GBK; kk += 16) {
            uint32_t af[4][4], bf[4][2];
            #pragma unroll
            for (int i = 0; i < 4; i++)
                ldmx4(af[i][0], af[i][1], af[i][2], af[i][3],
                      a_s + (uint32_t)(i * 16 * PADK + kk) * 2);
            #pragma unroll
            for (int jp = 0; jp < 2; jp++)
                ldmx4(bf[2*jp][0], bf[2*jp][1], bf[2*jp+1][0], bf[2*jp+1][1],
                      b_s + (uint32_t)(jp * 16 * PADK + kk) * 2);
            #pragma unroll
            for (int i = 0; i < 4; i++)
                #pragma unroll
                for (int j = 0; j < 4; j++)
                    asm volatile(
                        "mma.sync.aligned.m16n8k16.row.col.f32.bf16.bf16.f32 "
                        "{%0,%1,%2,%3}, {%4,%5,%6,%7}, {%8,%9}, {%0,%1,%2,%3};"
                        : "+f"(acc[i][j][0]), "+f"(acc[i][j][1]),
                          "+f"(acc[i][j][2]), "+f"(acc[i][j][3])
                        : "r"(af[i][0]), "r"(af[i][1]), "r"(af[i][2]), "r"(af[i][3]),
                          "r"(bf[j][0]), "r"(bf[j][1]));
        }

        if (it + 3 < NIT) LOAD_STAGE((it + 3) & (STG - 1), (it + 3) * GBK);
        asm volatile("cp.async.commit_group;");
    }

    #pragma unroll
    for (int i = 0; i < 4; i++) {
        int r = bm + wm * 64 + i * 16 + g;
        #pragma unroll
        for (int j = 0; j < 4; j++) {
            int c = bn + wn * 32 + j * 8 + 2 * tig;
            *(float2*)&Y[(size_t)r * N + c]       = make_float2(acc[i][j][0], acc[i][j][1]);
            *(float2*)&Y[(size_t)(r + 8) * N + c] = make_float2(acc[i][j][2], acc[i][j][3]);
        }
    }
#undef LOAD_STAGE
}

// ---------------- windowed ALiBi flash attention ----------------------------
// float4-vectorized smem, shuffle softmax, fused bf16x3 split output.
__global__ __launch_bounds__(256) void attn_win(
    const float* __restrict__ q, const float* __restrict__ k,
    const float* __restrict__ v, const float* __restrict__ slopes,
    __nv_bfloat16* __restrict__ oa)
{
    extern __shared__ float smf[];
    float (*Qs)[APAD] = (float (*)[APAD]) smf;
    float (*Ks)[APAD] = (float (*)[APAD])(smf + 1 * BQ * APAD);
    float (*Vs)[APAD] = (float (*)[APAD])(smf + 2 * BQ * APAD);
    float (*Ss)[APAD] = (float (*)[APAD])(smf + 3 * BQ * APAD);

    int qt = blockIdx.x, h = blockIdx.y, b = blockIdx.z;
    int q0 = qt * BQ;
    int tid = threadIdx.x;
    int ty = tid >> 4, tx = tid & 15;
    float slope = slopes[h];

    // load Q tile (float4), pre-scaled
    #pragma unroll
    for (int i = 0; i < 4; i++) {
        int idx = tid + i * 256;              // 1024 float4s
        int r = idx >> 4, cg = (idx & 15) * 4;
        float4 qv = *(const float4*)(q + ((size_t)b * S_LEN + q0 + r) * NQKV
                                       + h * DKH + cg);
        Qs[r][cg] = qv.x * 0.125f; Qs[r][cg+1] = qv.y * 0.125f;
        Qs[r][cg+2] = qv.z * 0.125f; Qs[r][cg+3] = qv.w * 0.125f;
    }

    float m_r[4], l_r[4];
    #pragma unroll
    for (int i = 0; i < 4; i++) { m_r[i] = -INFINITY; l_r[i] = 0.f; }

    float acc[4][4];
    #pragma unroll
    for (int i = 0; i < 4; i++)
        #pragma unroll
        for (int j = 0; j < 4; j++) acc[i][j] = 0.f;

    int kstart = q0 - HALF_WIN; if (kstart < 0) kstart = 0;
    int kend   = q0 + BQ + HALF_WIN; if (kend > S_LEN) kend = S_LEN;

    for (int kc = kstart; kc < kend; kc += BKC) {
        __syncthreads();
        #pragma unroll
        for (int i = 0; i < 4; i++) {
            int idx = tid + i * 256;
            int r = idx >> 4, cg = (idx & 15) * 4;
            size_t base = ((size_t)b * S_LEN + kc + r) * NQKV + h * DKH + cg;
            *(float4*)&Ks[r][cg] = *(const float4*)(k + base);
            *(float4*)&Vs[r][cg] = *(const float4*)(v + base);
        }
        __syncthreads();

        // S = Q @ K^T, float4 fragments
        float sacc[4][4];
        #pragma unroll
        for (int i = 0; i < 4; i++)
            #pragma unroll
            for (int j = 0; j < 4; j++) sacc[i][j] = 0.f;

        #pragma unroll
        for (int kk = 0; kk < DKH; kk += 4) {
            float4 a[4], bb[4];
            #pragma unroll
            for (int i = 0; i < 4; i++) a[i]  = *(const float4*)&Qs[4*ty+i][kk];
            #pragma unroll
            for (int j = 0; j < 4; j++) bb[j] = *(const float4*)&Ks[4*tx+j][kk];
            #pragma unroll
            for (int i = 0; i < 4; i++)
                #pragma unroll
                for (int j = 0; j < 4; j++)
                    sacc[i][j] += a[i].x * bb[j].x + a[i].y * bb[j].y
                                + a[i].z * bb[j].z + a[i].w * bb[j].w;
        }

        // bias + mask
        #pragma unroll
        for (int i = 0; i < 4; i++) {
            int qp = q0 + 4*ty + i;
            #pragma unroll
            for (int j = 0; j < 4; j++) {
                int kp = kc + 4*tx + j;
                int d = qp - kp;
                float sv = sacc[i][j] + slope * (float)d;
                if (d > HALF_WIN || d < -HALF_WIN) sv = -INFINITY;
                sacc[i][j] = sv;
            }
        }

        // shuffle softmax (16 lanes sharing ty are a contiguous half-warp)
        #pragma unroll
        for (int i = 0; i < 4; i++) {
            float mx = fmaxf(fmaxf(sacc[i][0], sacc[i][1]),
                             fmaxf(sacc[i][2], sacc[i][3]));
            #pragma unroll
            for (int off = 8; off >= 1; off >>= 1)
                mx = fmaxf(mx, __shfl_xor_sync(0xffffffffu, mx, off));
            float mnew = fmaxf(m_r[i], mx);

            float alpha, lsum = 0.f;
            float4 p;
            if (mnew == -INFINITY) {
                alpha = 1.f;
                p = make_float4(0.f, 0.f, 0.f, 0.f);
            } else {
                alpha = __expf(m_r[i] - mnew);
                p.x = __expf(sacc[i][0] - mnew);
                p.y = __expf(sacc[i][1] - mnew);
                p.z = __expf(sacc[i][2] - mnew);
                p.w = __expf(sacc[i][3] - mnew);
                lsum = p.x + p.y + p.z + p.w;
            }
            #pragma unroll
            for (int off = 8; off >= 1; off >>= 1)
                lsum += __shfl_xor_sync(0xffffffffu, lsum, off);

            l_r[i] = l_r[i] * alpha + lsum;
            m_r[i] = mnew;
            *(float4*)&Ss[4*ty+i][4*tx] = p;
            #pragma unroll
            for (int j = 0; j < 4; j++) acc[i][j] *= alpha;
        }
        __syncthreads();

        // O += P @ V, float4 fragments
        #pragma unroll
        for (int kk = 0; kk < BKC; kk += 4) {
            float4 p[4], vr[4];
            #pragma unroll
            for (int i = 0; i < 4; i++) p[i]  = *(const float4*)&Ss[4*ty+i][kk];
            #pragma unroll
            for (int t = 0; t < 4; t++) vr[t] = *(const float4*)&Vs[kk+t][4*tx];
            const float* v0 = (const float*)&vr[0];
            const float* v1 = (const float*)&vr[1];
            const float* v2 = (const float*)&vr[2];
            const float* v3 = (const float*)&vr[3];
            #pragma unroll
            for (int i = 0; i < 4; i++) {
                #pragma unroll
                for (int j = 0; j < 4; j++)
                    acc[i][j] += p[i].x * v0[j] + p[i].y * v1[j]
                               + p[i].z * v2[j] + p[i].w * v3[j];
            }
        }
    }

    // epilogue: bf16x3 split output [hi | lo | hi] directly into aoa
    #pragma unroll
    for (int i = 0; i < 4; i++) {
        int r = q0 + 4*ty + i;
        float inv = 1.f / l_r[i];
        float of[4];
        __nv_bfloat16 hi[4], lo[4];
        #pragma unroll
        for (int j = 0; j < 4; j++) {
            of[j] = acc[i][j] * inv;
            hi[j] = __float2bfloat16(of[j]);
            lo[j] = __float2bfloat16(of[j] - __bfloat162float(hi[j]));
        }
        __nv_bfloat162 hp0 = __halves2bfloat162(hi[0], hi[1]);
        __nv_bfloat162 hp1 = __halves2bfloat162(hi[2], hi[3]);
        __nv_bfloat162 lp0 = __halves2bfloat162(lo[0], lo[1]);
        __nv_bfloat162 lp1 = __halves2bfloat162(lo[2], lo[3]);
        size_t rowb = ((size_t)b * S_LEN + r) * K3 + h * DKH + 4*tx;
        __nv_bfloat162* o0 = (__nv_bfloat162*)(oa + rowb);
        __nv_bfloat162* o1 = (__nv_bfloat162*)(oa + rowb + D_MODEL);
        __nv_bfloat162* o2 = (__nv_bfloat162*)(oa + rowb + 2 * D_MODEL);
        o0[0] = hp0; o0[1] = hp1;
        o1[0] = lp0; o1[1] = lp1;
        o2[0] = hp0; o2[1] = hp1;
    }
}

// ---------------------------------------------------------------------------
extern "C" void kernel_launch(void* const* d_in, const int* in_sizes, int n_in,
                              void* d_out, int out_size)
{
    const float* x      = (const float*)d_in[0];
    const float* Wq     = (const float*)d_in[1];
    const float* Wk     = (const float*)d_in[2];
    const float* Wv     = (const float*)d_in[3];
    const float* Wo     = (const float*)d_in[4];
    const float* slopes = (const float*)d_in[5];
    float* out = (float*)d_out;

    float *qkv;
    __nv_bfloat16 *xa, *aoa, *wqkv, *wo;
    cudaGetSymbolAddress((void**)&qkv,  g_qkv);
    cudaGetSymbolAddress((void**)&xa,   g_xa);
    cudaGetSymbolAddress((void**)&aoa,  g_aoa);
    cudaGetSymbolAddress((void**)&wqkv, g_wqkv);
    cudaGetSymbolAddress((void**)&wo,   g_wo);

    conv_split<<<MROWS, 256>>>(x, xa, 0);
    conv_split<<<D_MODEL, 256>>>(Wq, wqkv + 0 * (size_t)D_MODEL * K3, 1);
    conv_split<<<D_MODEL, 256>>>(Wk, wqkv + 1 * (size_t)D_MODEL * K3, 1);
    conv_split<<<D_MODEL, 256>>>(Wv, wqkv + 2 * (size_t)D_MODEL * K3, 1);
    conv_split<<<D_MODEL, 256>>>(Wo, wo, 1);

    cudaFuncSetAttribute(gemm_mma, cudaFuncAttributeMaxDynamicSharedMemorySize,
                         SMEM_GEMM);

    gemm_mma<<<dim3(NQKV / GBN, MROWS / GBM), 256, SMEM_GEMM>>>(xa, wqkv, qkv, NQKV);

    size_t smem = (size_t)4 * BQ * APAD * sizeof(float);   // 69632 B
    cudaFuncSetAttribute(attn_win, cudaFuncAttributeMaxDynamicSharedMemorySize,
                         (int)smem);
    attn_win<<<dim3(S_LEN / BQ, NHEADS, BATCH), 256, smem>>>(
        qkv, qkv + D_MODEL, qkv + 2 * D_MODEL, slopes, aoa);

    gemm_mma<<<dim3(D_MODEL / GBN, MROWS / GBM), 256, SMEM_GEMM>>>(aoa, wo, out, D_MODEL);
}

// round 6
// speedup vs baseline: 1.2264x; 1.2264x over previous
#include <cuda_runtime.h>
#include <cuda_bf16.h>
#include <stdint.h>
#include <math.h>

#define S_LEN   2048
#define D_MODEL 1024
#define NHEADS  16
#define DKH     64
#define HALF_WIN 128
#define BQ      64
#define BKC     64
#define BATCH   2
#define MROWS   (BATCH * S_LEN)   // 4096
#define K3      (3 * D_MODEL)     // 3072
#define NQKV    3072

// ---------------- scratch (static device globals; no allocation) -----------
__device__ float g_qkv[MROWS * NQKV];                // fused q|k|v fp32
__device__ float g_ao [MROWS * D_MODEL];
__device__ __nv_bfloat16 g_xa  [MROWS * K3];         // x split [hi|lo|hi]
__device__ __nv_bfloat16 g_aoa [MROWS * K3];         // attn-out split
__device__ __nv_bfloat16 g_wqkv[NQKV * K3];          // [Wq;Wk;Wv] split [hi|hi|lo]
__device__ __nv_bfloat16 g_wo  [D_MODEL * K3];       // Wo split

// ---------------- fp32 -> bf16x3 split conversion ---------------------------
__device__ __forceinline__ void split_row(
    const float* __restrict__ in, __nv_bfloat16* __restrict__ out,
    int r, int c, int modeB)
{
    float4 v = *(const float4*)(in + (size_t)r * D_MODEL + c);
    float f[4] = {v.x, v.y, v.z, v.w};
    __nv_bfloat16 hi[4], lo[4];
    #pragma unroll
    for (int j = 0; j < 4; j++) {
        hi[j] = __float2bfloat16(f[j]);
        lo[j] = __float2bfloat16(f[j] - __bfloat162float(hi[j]));
    }
    __nv_bfloat162 hp0 = __halves2bfloat162(hi[0], hi[1]);
    __nv_bfloat162 hp1 = __halves2bfloat162(hi[2], hi[3]);
    __nv_bfloat162 lp0 = __halves2bfloat162(lo[0], lo[1]);
    __nv_bfloat162 lp1 = __halves2bfloat162(lo[2], lo[3]);
    __nv_bfloat162* o0 = (__nv_bfloat162*)(out + (size_t)r * K3 + c);
    __nv_bfloat162* o1 = (__nv_bfloat162*)(out + (size_t)r * K3 + D_MODEL + c);
    __nv_bfloat162* o2 = (__nv_bfloat162*)(out + (size_t)r * K3 + 2 * D_MODEL + c);
    o0[0] = hp0; o0[1] = hp1;
    if (modeB) { o1[0] = hp0; o1[1] = hp1; o2[0] = lp0; o2[1] = lp1; }
    else       { o1[0] = lp0; o1[1] = lp1; o2[0] = hp0; o2[1] = hp1; }
}

__global__ __launch_bounds__(256) void conv_split(
    const float* __restrict__ in, __nv_bfloat16* __restrict__ out, int modeB)
{
    split_row(in, out, blockIdx.x, threadIdx.x * 4, modeB);
}

// all four weights in one launch: grid (1024, 4)
__global__ __launch_bounds__(256) void conv_split_w(
    const float* __restrict__ Wq, const float* __restrict__ Wk,
    const float* __restrict__ Wv, const float* __restrict__ Wo,
    __nv_bfloat16* __restrict__ wqkv, __nv_bfloat16* __restrict__ wo)
{
    int w = blockIdx.y;
    const float* src = (w == 0) ? Wq : (w == 1) ? Wk : (w == 2) ? Wv : Wo;
    __nv_bfloat16* dst = (w == 3) ? wo : wqkv + (size_t)w * D_MODEL * K3;
    split_row(src, dst, blockIdx.x, threadIdx.x * 4, 1);
}

// ---------------- mma.sync bf16 GEMM: Y[M,N] = A[M,K3] @ B[N,K3]^T ----------
#define GBM 128
#define GBN 128
#define GBK 64
#define PADK 72                    // halves per smem row (64 + 8 pad)
#define STG 3
#define SMEM_GEMM (STG * (GBM + GBN) * PADK * 2)   // 110592 B

__device__ __forceinline__ uint32_t s2u(const void* p) {
    uint32_t a;
    asm("{ .reg .u64 t; cvta.to.shared.u64 t, %1; cvt.u32.u64 %0, t; }"
        : "=r"(a) : "l"(p));
    return a;
}
__device__ __forceinline__ void cp16(uint32_t dst, const void* src) {
    asm volatile("cp.async.cg.shared.global [%0], [%1], 16;" :: "r"(dst), "l"(src));
}
__device__ __forceinline__ void ldmx4(uint32_t& r0, uint32_t& r1, uint32_t& r2,
                                      uint32_t& r3, uint32_t addr) {
    asm volatile("ldmatrix.sync.aligned.m8n8.x4.shared.b16 {%0,%1,%2,%3}, [%4];"
                 : "=r"(r0), "=r"(r1), "=r"(r2), "=r"(r3) : "r"(addr));
}

__global__ __launch_bounds__(256, 2) void gemm_mma(
    const __nv_bfloat16* __restrict__ A,
    const __nv_bfloat16* __restrict__ B,
    float* __restrict__ Y, int N)
{
    extern __shared__ __nv_bfloat16 smem_g[];

    int tid = threadIdx.x;
    int wid = tid >> 5, lane = tid & 31;
    int wm = wid & 1, wn = wid >> 1;            // 2x4 warp grid
    int bm = blockIdx.y * GBM, bn = blockIdx.x * GBN;
    int g = lane >> 2, tig = lane & 3;

    int lrow = tid >> 3;                        // 0..31 (row group base)
    int lch  = tid & 7;                         // 0..7 (16B chunk in 64-half slab)

    uint32_t as_base = s2u(smem_g);
    uint32_t bs_base = as_base + STG * GBM * PADK * 2;

    uint32_t a_ld = as_base +
        ((uint32_t)(wm * 64 + (lane & 15)) * PADK + ((lane >> 4) * 8)) * 2;
    uint32_t b_ld = bs_base +
        ((uint32_t)(wn * 32 + ((lane >> 4) * 8) + (lane & 7)) * PADK +
         (((lane >> 3) & 1) * 8)) * 2;

    const int NIT = K3 / GBK;                   // 48
    const uint32_t ASTG = GBM * PADK * 2;
    const uint32_t BSTG = GBN * PADK * 2;

#define LOAD_STAGE(s, k0)                                                     \
    do {                                                                      \
        _Pragma("unroll")                                                     \
        for (int i = 0; i < 4; i++) {                                         \
            int row = lrow + i * 32;                                          \
            cp16(as_base + (uint32_t)(s) * ASTG + (row * PADK + lch * 8) * 2, \
                 A + (size_t)(bm + row) * K3 + (k0) + lch * 8);               \
            cp16(bs_base + (uint32_t)(s) * BSTG + (row * PADK + lch * 8) * 2, \
                 B + (size_t)(bn + row) * K3 + (k0) + lch * 8);               \
        }                                                                     \
    } while (0)

    LOAD_STAGE(0, 0);
    asm volatile("cp.async.commit_group;");
    LOAD_STAGE(1, GBK);
    asm volatile("cp.async.commit_group;");

    float acc[4][4][4];
    #pragma unroll
    for (int i = 0; i < 4; i++)
        #pragma unroll
        for (int j = 0; j < 4; j++)
            #pragma unroll
            for (int t = 0; t < 4; t++) acc[i][j][t] = 0.f;

    int s = 0;
    for (int it = 0; it < NIT; it++) {
        asm volatile("cp.async.wait_group 1;");
        __syncthreads();

        uint32_t a_s = a_ld + s * ASTG;
        uint32_t b_s = b_ld + s * BSTG;

        #pragma unroll
        for (int kk = 0; kk < GBK; kk += 16) {
            uint32_t af[4][4], bf[4][2];
            #pragma unroll
            for (int i = 0; i < 4; i++)
                ldmx4(af[i][0], af[i][1], af[i][2], af[i][3],
                      a_s + (uint32_t)(i * 16 * PADK + kk) * 2);
            #pragma unroll
            for (int jp = 0; jp < 2; jp++)
                ldmx4(bf[2*jp][0], bf[2*jp][1], bf[2*jp+1][0], bf[2*jp+1][1],
                      b_s + (uint32_t)(jp * 16 * PADK + kk) * 2);
            #pragma unroll
            for (int i = 0; i < 4; i++)
                #pragma unroll
                for (int j = 0; j < 4; j++)
                    asm volatile(
                        "mma.sync.aligned.m16n8k16.row.col.f32.bf16.bf16.f32 "
                        "{%0,%1,%2,%3}, {%4,%5,%6,%7}, {%8,%9}, {%0,%1,%2,%3};"
                        : "+f"(acc[i][j][0]), "+f"(acc[i][j][1]),
                          "+f"(acc[i][j][2]), "+f"(acc[i][j][3])
                        : "r"(af[i][0]), "r"(af[i][1]), "r"(af[i][2]), "r"(af[i][3]),
                          "r"(bf[j][0]), "r"(bf[j][1]));
        }

        int s2 = s + 2; if (s2 >= STG) s2 -= STG;
        if (it + 2 < NIT) LOAD_STAGE(s2, (it + 2) * GBK);
        asm volatile("cp.async.commit_group;");
        s = s + 1; if (s >= STG) s = 0;
    }

    #pragma unroll
    for (int i = 0; i < 4; i++) {
        int r = bm + wm * 64 + i * 16 + g;
        #pragma unroll
        for (int j = 0; j < 4; j++) {
            int c = bn + wn * 32 + j * 8 + 2 * tig;
            *(float2*)&Y[(size_t)r * N + c]       = make_float2(acc[i][j][0], acc[i][j][1]);
            *(float2*)&Y[(size_t)(r + 8) * N + c] = make_float2(acc[i][j][2], acc[i][j][3]);
        }
    }
#undef LOAD_STAGE
}

// ---------------- windowed ALiBi flash attention (R4 proven version) -------
__global__ __launch_bounds__(256) void attn_win(
    const float* __restrict__ q, const float* __restrict__ k,
    const float* __restrict__ v, const float* __restrict__ slopes,
    float* __restrict__ o)
{
    extern __shared__ float smf[];
    float (*Qs)[DKH + 1] = (float (*)[DKH + 1]) smf;
    float (*Ks)[DKH + 1] = (float (*)[DKH + 1])(smf + 1 * BQ * (DKH + 1));
    float (*Vs)[DKH + 1] = (float (*)[DKH + 1])(smf + 2 * BQ * (DKH + 1));
    float (*Ss)[BKC + 1] = (float (*)[BKC + 1])(smf + 3 * BQ * (DKH + 1));

    int qt = blockIdx.x, h = blockIdx.y, b = blockIdx.z;
    int q0 = qt * BQ;
    int tid = threadIdx.x;
    int ty = tid >> 4, tx = tid & 15;
    float slope = slopes[h];

    for (int i = tid; i < BQ * DKH; i += 256) {
        int r = i >> 6, c = i & 63;
        Qs[r][c] = q[((size_t)b * S_LEN + q0 + r) * NQKV + h * DKH + c] * 0.125f;
    }

    float m_r[4], l_r[4];
    #pragma unroll
    for (int i = 0; i < 4; i++) { m_r[i] = -INFINITY; l_r[i] = 0.f; }

    float acc[4][4];
    #pragma unroll
    for (int i = 0; i < 4; i++)
        #pragma unroll
        for (int j = 0; j < 4; j++) acc[i][j] = 0.f;

    int kstart = q0 - HALF_WIN; if (kstart < 0) kstart = 0;
    int kend   = q0 + BQ + HALF_WIN; if (kend > S_LEN) kend = S_LEN;

    for (int kc = kstart; kc < kend; kc += BKC) {
        __syncthreads();
        for (int i = tid; i < BKC * DKH; i += 256) {
            int r = i >> 6, c = i & 63;
            size_t base = ((size_t)b * S_LEN + kc + r) * NQKV + h * DKH + c;
            Ks[r][c] = k[base];
            Vs[r][c] = v[base];
        }
        __syncthreads();

        float sacc[4][4];
        #pragma unroll
        for (int i = 0; i < 4; i++)
            #pragma unroll
            for (int j = 0; j < 4; j++) sacc[i][j] = 0.f;

        #pragma unroll 8
        for (int kk = 0; kk < DKH; kk++) {
            float a0 = Qs[4*ty+0][kk], a1 = Qs[4*ty+1][kk];
            float a2 = Qs[4*ty+2][kk], a3 = Qs[4*ty+3][kk];
            float b0 = Ks[4*tx+0][kk], b1 = Ks[4*tx+1][kk];
            float b2 = Ks[4*tx+2][kk], b3 = Ks[4*tx+3][kk];
            sacc[0][0] += a0*b0; sacc[0][1] += a0*b1; sacc[0][2] += a0*b2; sacc[0][3] += a0*b3;
            sacc[1][0] += a1*b0; sacc[1][1] += a1*b1; sacc[1][2] += a1*b2; sacc[1][3] += a1*b3;
            sacc[2][0] += a2*b0; sacc[2][1] += a2*b1; sacc[2][2] += a2*b2; sacc[2][3] += a2*b3;
            sacc[3][0] += a3*b0; sacc[3][1] += a3*b1; sacc[3][2] += a3*b2; sacc[3][3] += a3*b3;
        }

        #pragma unroll
        for (int i = 0; i < 4; i++) {
            int qp = q0 + 4*ty + i;
            #pragma unroll
            for (int j = 0; j < 4; j++) {
                int kp = kc + 4*tx + j;
                int d = qp - kp;
                float sv = sacc[i][j] + slope * (float)d;
                if (d > HALF_WIN || d < -HALF_WIN) sv = -INFINITY;
                sacc[i][j] = sv;
            }
        }

        #pragma unroll
        for (int i = 0; i < 4; i++) {
            float mx = fmaxf(fmaxf(sacc[i][0], sacc[i][1]),
                             fmaxf(sacc[i][2], sacc[i][3]));
            #pragma unroll
            for (int off = 8; off >= 1; off >>= 1)
                mx = fmaxf(mx, __shfl_xor_sync(0xffffffffu, mx, off));
            float mnew = fmaxf(m_r[i], mx);

            float alpha, lsum = 0.f;
            float p[4];
            if (mnew == -INFINITY) {
                alpha = 1.f;
                p[0] = p[1] = p[2] = p[3] = 0.f;
            } else {
                alpha = __expf(m_r[i] - mnew);
                #pragma unroll
                for (int j = 0; j < 4; j++) {
                    p[j] = __expf(sacc[i][j] - mnew);
                    lsum += p[j];
                }
            }
            #pragma unroll
            for (int off = 8; off >= 1; off >>= 1)
                lsum += __shfl_xor_sync(0xffffffffu, lsum, off);

            l_r[i] = l_r[i] * alpha + lsum;
            m_r[i] = mnew;
            #pragma unroll
            for (int j = 0; j < 4; j++) {
                Ss[4*ty+i][4*tx+j] = p[j];
                acc[i][j] *= alpha;
            }
        }
        __syncthreads();

        #pragma unroll 8
        for (int kk = 0; kk < BKC; kk++) {
            float p0 = Ss[4*ty+0][kk], p1 = Ss[4*ty+1][kk];
            float p2 = Ss[4*ty+2][kk], p3 = Ss[4*ty+3][kk];
            float v0 = Vs[kk][4*tx+0], v1 = Vs[kk][4*tx+1];
            float v2 = Vs[kk][4*tx+2], v3 = Vs[kk][4*tx+3];
            acc[0][0] += p0*v0; acc[0][1] += p0*v1; acc[0][2] += p0*v2; acc[0][3] += p0*v3;
            acc[1][0] += p1*v0; acc[1][1] += p1*v1; acc[1][2] += p1*v2; acc[1][3] += p1*v3;
            acc[2][0] += p2*v0; acc[2][1] += p2*v1; acc[2][2] += p2*v2; acc[2][3] += p2*v3;
            acc[3][0] += p3*v0; acc[3][1] += p3*v1; acc[3][2] += p3*v2; acc[3][3] += p3*v3;
        }
    }

    #pragma unroll
    for (int i = 0; i < 4; i++) {
        int r = 4*ty + i;
        float inv = 1.f / l_r[i];
        #pragma unroll
        for (int j = 0; j < 4; j++)
            o[((size_t)b * S_LEN + q0 + r) * D_MODEL + h * DKH + 4*tx + j] =
                acc[i][j] * inv;
    }
}

// ---------------------------------------------------------------------------
extern "C" void kernel_launch(void* const* d_in, const int* in_sizes, int n_in,
                              void* d_out, int out_size)
{
    const float* x      = (const float*)d_in[0];
    const float* Wq     = (const float*)d_in[1];
    const float* Wk     = (const float*)d_in[2];
    const float* Wv     = (const float*)d_in[3];
    const float* Wo     = (const float*)d_in[4];
    const float* slopes = (const float*)d_in[5];
    float* out = (float*)d_out;

    float *qkv, *aob;
    __nv_bfloat16 *xa, *aoa, *wqkv, *wo;
    cudaGetSymbolAddress((void**)&qkv,  g_qkv);
    cudaGetSymbolAddress((void**)&aob,  g_ao);
    cudaGetSymbolAddress((void**)&xa,   g_xa);
    cudaGetSymbolAddress((void**)&aoa,  g_aoa);
    cudaGetSymbolAddress((void**)&wqkv, g_wqkv);
    cudaGetSymbolAddress((void**)&wo,   g_wo);

    conv_split<<<MROWS, 256>>>(x, xa, 0);
    conv_split_w<<<dim3(D_MODEL, 4), 256>>>(Wq, Wk, Wv, Wo, wqkv, wo);

    cudaFuncSetAttribute(gemm_mma, cudaFuncAttributeMaxDynamicSharedMemorySize,
                         SMEM_GEMM);

    gemm_mma<<<dim3(NQKV / GBN, MROWS / GBM), 256, SMEM_GEMM>>>(xa, wqkv, qkv, NQKV);

    size_t smem = (size_t)4 * BQ * (DKH + 1) * sizeof(float);
    cudaFuncSetAttribute(attn_win, cudaFuncAttributeMaxDynamicSharedMemorySize,
                         (int)smem);
    attn_win<<<dim3(S_LEN / BQ, NHEADS, BATCH), 256, smem>>>(
        qkv, qkv + D_MODEL, qkv + 2 * D_MODEL, slopes, aob);

    conv_split<<<MROWS, 256>>>(aob, aoa, 0);

    gemm_mma<<<dim3(D_MODEL / GBN, MROWS / GBM), 256, SMEM_GEMM>>>(aoa, wo, out, D_MODEL);
}

// round 7
// speedup vs baseline: 1.2409x; 1.0118x over previous
#include <cuda_runtime.h>
#include <cuda_bf16.h>
#include <stdint.h>
#include <math.h>

#define S_LEN   2048
#define D_MODEL 1024
#define NHEADS  16
#define DKH     64
#define HALF_WIN 128
#define BQ      64
#define BKC     64
#define BATCH   2
#define MROWS   (BATCH * S_LEN)   // 4096
#define K3      (3 * D_MODEL)     // 3072
#define NQKV    3072

// attention smem row pads
#define QKPAD 65                   // scalar-access tiles (Q, K)
#define VSPAD 68                   // float4-access tiles (V, S)

// ---------------- scratch (static device globals; no allocation) -----------
__device__ float g_qkv[MROWS * NQKV];                // fused q|k|v fp32
__device__ float g_ao [MROWS * D_MODEL];
__device__ __nv_bfloat16 g_xa  [MROWS * K3];         // x split [hi|lo|hi]
__device__ __nv_bfloat16 g_aoa [MROWS * K3];         // attn-out split
__device__ __nv_bfloat16 g_wqkv[NQKV * K3];          // [Wq;Wk;Wv] split [hi|hi|lo]
__device__ __nv_bfloat16 g_wo  [D_MODEL * K3];       // Wo split

// ---------------- fp32 -> bf16x3 split conversion ---------------------------
__device__ __forceinline__ void split_row(
    const float* __restrict__ in, __nv_bfloat16* __restrict__ out,
    int r, int c, int modeB)
{
    float4 v = *(const float4*)(in + (size_t)r * D_MODEL + c);
    float f[4] = {v.x, v.y, v.z, v.w};
    __nv_bfloat16 hi[4], lo[4];
    #pragma unroll
    for (int j = 0; j < 4; j++) {
        hi[j] = __float2bfloat16(f[j]);
        lo[j] = __float2bfloat16(f[j] - __bfloat162float(hi[j]));
    }
    __nv_bfloat162 hp0 = __halves2bfloat162(hi[0], hi[1]);
    __nv_bfloat162 hp1 = __halves2bfloat162(hi[2], hi[3]);
    __nv_bfloat162 lp0 = __halves2bfloat162(lo[0], lo[1]);
    __nv_bfloat162 lp1 = __halves2bfloat162(lo[2], lo[3]);
    __nv_bfloat162* o0 = (__nv_bfloat162*)(out + (size_t)r * K3 + c);
    __nv_bfloat162* o1 = (__nv_bfloat162*)(out + (size_t)r * K3 + D_MODEL + c);
    __nv_bfloat162* o2 = (__nv_bfloat162*)(out + (size_t)r * K3 + 2 * D_MODEL + c);
    o0[0] = hp0; o0[1] = hp1;
    if (modeB) { o1[0] = hp0; o1[1] = hp1; o2[0] = lp0; o2[1] = lp1; }
    else       { o1[0] = lp0; o1[1] = lp1; o2[0] = hp0; o2[1] = hp1; }
}

__global__ __launch_bounds__(256) void conv_split(
    const float* __restrict__ in, __nv_bfloat16* __restrict__ out, int modeB)
{
    split_row(in, out, blockIdx.x, threadIdx.x * 4, modeB);
}

__global__ __launch_bounds__(256) void conv_split_w(
    const float* __restrict__ Wq, const float* __restrict__ Wk,
    const float* __restrict__ Wv, const float* __restrict__ Wo,
    __nv_bfloat16* __restrict__ wqkv, __nv_bfloat16* __restrict__ wo)
{
    int w = blockIdx.y;
    const float* src = (w == 0) ? Wq : (w == 1) ? Wk : (w == 2) ? Wv : Wo;
    __nv_bfloat16* dst = (w == 3) ? wo : wqkv + (size_t)w * D_MODEL * K3;
    split_row(src, dst, blockIdx.x, threadIdx.x * 4, 1);
}

// ---------------- mma.sync bf16 GEMM: Y[M,N] = A[M,K3] @ B[N,K3]^T ----------
#define GBM 128
#define GBN 128
#define GBK 64
#define PADK 72
#define STG 3
#define SMEM_GEMM (STG * (GBM + GBN) * PADK * 2)   // 110592 B

__device__ __forceinline__ uint32_t s2u(const void* p) {
    uint32_t a;
    asm("{ .reg .u64 t; cvta.to.shared.u64 t, %1; cvt.u32.u64 %0, t; }"
        : "=r"(a) : "l"(p));
    return a;
}
__device__ __forceinline__ void cp16(uint32_t dst, const void* src) {
    asm volatile("cp.async.cg.shared.global [%0], [%1], 16;" :: "r"(dst), "l"(src));
}
__device__ __forceinline__ void ldmx4(uint32_t& r0, uint32_t& r1, uint32_t& r2,
                                      uint32_t& r3, uint32_t addr) {
    asm volatile("ldmatrix.sync.aligned.m8n8.x4.shared.b16 {%0,%1,%2,%3}, [%4];"
                 : "=r"(r0), "=r"(r1), "=r"(r2), "=r"(r3) : "r"(addr));
}

__global__ __launch_bounds__(256, 2) void gemm_mma(
    const __nv_bfloat16* __restrict__ A,
    const __nv_bfloat16* __restrict__ B,
    float* __restrict__ Y, int N)
{
    extern __shared__ __nv_bfloat16 smem_g[];

    int tid = threadIdx.x;
    int wid = tid >> 5, lane = tid & 31;
    int wm = wid & 1, wn = wid >> 1;
    int bm = blockIdx.y * GBM, bn = blockIdx.x * GBN;
    int g = lane >> 2, tig = lane & 3;

    int lrow = tid >> 3;
    int lch  = tid & 7;

    uint32_t as_base = s2u(smem_g);
    uint32_t bs_base = as_base + STG * GBM * PADK * 2;

    uint32_t a_ld = as_base +
        ((uint32_t)(wm * 64 + (lane & 15)) * PADK + ((lane >> 4) * 8)) * 2;
    uint32_t b_ld = bs_base +
        ((uint32_t)(wn * 32 + ((lane >> 4) * 8) + (lane & 7)) * PADK +
         (((lane >> 3) & 1) * 8)) * 2;

    const int NIT = K3 / GBK;                   // 48
    const uint32_t ASTG = GBM * PADK * 2;
    const uint32_t BSTG = GBN * PADK * 2;

#define LOAD_STAGE(s, k0)                                                     \
    do {                                                                      \
        _Pragma("unroll")                                                     \
        for (int i = 0; i < 4; i++) {                                         \
            int row = lrow + i * 32;                                          \
            cp16(as_base + (uint32_t)(s) * ASTG + (row * PADK + lch * 8) * 2, \
                 A + (size_t)(bm + row) * K3 + (k0) + lch * 8);               \
            cp16(bs_base + (uint32_t)(s) * BSTG + (row * PADK + lch * 8) * 2, \
                 B + (size_t)(bn + row) * K3 + (k0) + lch * 8);               \
        }                                                                     \
    } while (0)

    LOAD_STAGE(0, 0);
    asm volatile("cp.async.commit_group;");
    LOAD_STAGE(1, GBK);
    asm volatile("cp.async.commit_group;");

    float acc[4][4][4];
    #pragma unroll
    for (int i = 0; i < 4; i++)
        #pragma unroll
        for (int j = 0; j < 4; j++)
            #pragma unroll
            for (int t = 0; t < 4; t++) acc[i][j][t] = 0.f;

    int s = 0;
    for (int it = 0; it < NIT; it++) {
        asm volatile("cp.async.wait_group 1;");
        __syncthreads();

        uint32_t a_s = a_ld + s * ASTG;
        uint32_t b_s = b_ld + s * BSTG;

        #pragma unroll
        for (int kk = 0; kk < GBK; kk += 16) {
            uint32_t af[4][4], bf[4][2];
            #pragma unroll
            for (int i = 0; i < 4; i++)
                ldmx4(af[i][0], af[i][1], af[i][2], af[i][3],
                      a_s + (uint32_t)(i * 16 * PADK + kk) * 2);
            #pragma unroll
            for (int jp = 0; jp < 2; jp++)
                ldmx4(bf[2*jp][0], bf[2*jp][1], bf[2*jp+1][0], bf[2*jp+1][1],
                      b_s + (uint32_t)(jp * 16 * PADK + kk) * 2);
            #pragma unroll
            for (int i = 0; i < 4; i++)
                #pragma unroll
                for (int j = 0; j < 4; j++)
                    asm volatile(
                        "mma.sync.aligned.m16n8k16.row.col.f32.bf16.bf16.f32 "
                        "{%0,%1,%2,%3}, {%4,%5,%6,%7}, {%8,%9}, {%0,%1,%2,%3};"
                        : "+f"(acc[i][j][0]), "+f"(acc[i][j][1]),
                          "+f"(acc[i][j][2]), "+f"(acc[i][j][3])
                        : "r"(af[i][0]), "r"(af[i][1]), "r"(af[i][2]), "r"(af[i][3]),
                          "r"(bf[j][0]), "r"(bf[j][1]));
        }

        int s2 = s + 2; if (s2 >= STG) s2 -= STG;
        if (it + 2 < NIT) LOAD_STAGE(s2, (it + 2) * GBK);
        asm volatile("cp.async.commit_group;");
        s = s + 1; if (s >= STG) s = 0;
    }

    #pragma unroll
    for (int i = 0; i < 4; i++) {
        int r = bm + wm * 64 + i * 16 + g;
        #pragma unroll
        for (int j = 0; j < 4; j++) {
            int c = bn + wn * 32 + j * 8 + 2 * tig;
            *(float2*)&Y[(size_t)r * N + c]       = make_float2(acc[i][j][0], acc[i][j][1]);
            *(float2*)&Y[(size_t)(r + 8) * N + c] = make_float2(acc[i][j][2], acc[i][j][3]);
        }
    }
#undef LOAD_STAGE
}

// ---------------- windowed ALiBi flash attention ----------------------------
// Q/K scalar tiles (pad 65, proven), V/S float4 tiles (pad 68, row-contiguous).
__global__ __launch_bounds__(256, 3) void attn_win(
    const float* __restrict__ q, const float* __restrict__ k,
    const float* __restrict__ v, const float* __restrict__ slopes,
    float* __restrict__ o)
{
    extern __shared__ float smf[];
    float (*Qs)[QKPAD] = (float (*)[QKPAD]) smf;
    float (*Ks)[QKPAD] = (float (*)[QKPAD])(smf + BQ * QKPAD);
    float (*Vs)[VSPAD] = (float (*)[VSPAD])(smf + 2 * BQ * QKPAD);
    float (*Ss)[VSPAD] = (float (*)[VSPAD])(smf + 2 * BQ * QKPAD + BQ * VSPAD);

    int qt = blockIdx.x, h = blockIdx.y, b = blockIdx.z;
    int q0 = qt * BQ;
    int tid = threadIdx.x;
    int ty = tid >> 4, tx = tid & 15;
    float slope = slopes[h];

    for (int i = tid; i < BQ * DKH; i += 256) {
        int r = i >> 6, c = i & 63;
        Qs[r][c] = q[((size_t)b * S_LEN + q0 + r) * NQKV + h * DKH + c] * 0.125f;
    }

    float m_r[4], l_r[4];
    #pragma unroll
    for (int i = 0; i < 4; i++) { m_r[i] = -INFINITY; l_r[i] = 0.f; }

    float acc[4][4];
    #pragma unroll
    for (int i = 0; i < 4; i++)
        #pragma unroll
        for (int j = 0; j < 4; j++) acc[i][j] = 0.f;

    int kstart = q0 - HALF_WIN; if (kstart < 0) kstart = 0;
    int kend   = q0 + BQ + HALF_WIN; if (kend > S_LEN) kend = S_LEN;

    for (int kc = kstart; kc < kend; kc += BKC) {
        __syncthreads();
        // K: scalar, coalesced gmem, conflict-free STS (stride 1)
        for (int i = tid; i < BKC * DKH; i += 256) {
            int r = i >> 6, c = i & 63;
            Ks[r][c] = k[((size_t)b * S_LEN + kc + r) * NQKV + h * DKH + c];
        }
        // V: float4, contiguous STS.128
        #pragma unroll
        for (int i = 0; i < 4; i++) {
            int idx = tid + i * 256;         // 1024 chunks
            int r = idx >> 4, cg = (idx & 15) * 4;
            *(float4*)&Vs[r][cg] =
                *(const float4*)(v + ((size_t)b * S_LEN + kc + r) * NQKV + h * DKH + cg);
        }
        __syncthreads();

        // S = Q @ K^T (scalar, R6-proven pattern)
        float sacc[4][4];
        #pragma unroll
        for (int i = 0; i < 4; i++)
            #pragma unroll
            for (int j = 0; j < 4; j++) sacc[i][j] = 0.f;

        #pragma unroll 8
        for (int kk = 0; kk < DKH; kk++) {
            float a0 = Qs[4*ty+0][kk], a1 = Qs[4*ty+1][kk];
            float a2 = Qs[4*ty+2][kk], a3 = Qs[4*ty+3][kk];
            float b0 = Ks[4*tx+0][kk], b1 = Ks[4*tx+1][kk];
            float b2 = Ks[4*tx+2][kk], b3 = Ks[4*tx+3][kk];
            sacc[0][0] += a0*b0; sacc[0][1] += a0*b1; sacc[0][2] += a0*b2; sacc[0][3] += a0*b3;
            sacc[1][0] += a1*b0; sacc[1][1] += a1*b1; sacc[1][2] += a1*b2; sacc[1][3] += a1*b3;
            sacc[2][0] += a2*b0; sacc[2][1] += a2*b1; sacc[2][2] += a2*b2; sacc[2][3] += a2*b3;
            sacc[3][0] += a3*b0; sacc[3][1] += a3*b1; sacc[3][2] += a3*b2; sacc[3][3] += a3*b3;
        }

        #pragma unroll
        for (int i = 0; i < 4; i++) {
            int qp = q0 + 4*ty + i;
            #pragma unroll
            for (int j = 0; j < 4; j++) {
                int kp = kc + 4*tx + j;
                int d = qp - kp;
                float sv = sacc[i][j] + slope * (float)d;
                if (d > HALF_WIN || d < -HALF_WIN) sv = -INFINITY;
                sacc[i][j] = sv;
            }
        }

        // shuffle softmax over 16 lanes sharing ty
        #pragma unroll
        for (int i = 0; i < 4; i++) {
            float mx = fmaxf(fmaxf(sacc[i][0], sacc[i][1]),
                             fmaxf(sacc[i][2], sacc[i][3]));
            #pragma unroll
            for (int off = 8; off >= 1; off >>= 1)
                mx = fmaxf(mx, __shfl_xor_sync(0xffffffffu, mx, off));
            float mnew = fmaxf(m_r[i], mx);

            float alpha, lsum = 0.f;
            float4 p;
            if (mnew == -INFINITY) {
                alpha = 1.f;
                p = make_float4(0.f, 0.f, 0.f, 0.f);
            } else {
                alpha = __expf(m_r[i] - mnew);
                p.x = __expf(sacc[i][0] - mnew);
                p.y = __expf(sacc[i][1] - mnew);
                p.z = __expf(sacc[i][2] - mnew);
                p.w = __expf(sacc[i][3] - mnew);
                lsum = p.x + p.y + p.z + p.w;
            }
            #pragma unroll
            for (int off = 8; off >= 1; off >>= 1)
                lsum += __shfl_xor_sync(0xffffffffu, lsum, off);

            l_r[i] = l_r[i] * alpha + lsum;
            m_r[i] = mnew;
            *(float4*)&Ss[4*ty+i][4*tx] = p;
            #pragma unroll
            for (int j = 0; j < 4; j++) acc[i][j] *= alpha;
        }
        __syncthreads();

        // O += P @ V (float4: Ss broadcast reads, Vs contiguous reads)
        #pragma unroll
        for (int kk = 0; kk < BKC; kk += 4) {
            float4 p[4], vr[4];
            #pragma unroll
            for (int i = 0; i < 4; i++) p[i]  = *(const float4*)&Ss[4*ty+i][kk];
            #pragma unroll
            for (int t = 0; t < 4; t++) vr[t] = *(const float4*)&Vs[kk+t][4*tx];
            #pragma unroll
            for (int i = 0; i < 4; i++) {
                acc[i][0] += p[i].x * vr[0].x + p[i].y * vr[1].x
                           + p[i].z * vr[2].x + p[i].w * vr[3].x;
                acc[i][1] += p[i].x * vr[0].y + p[i].y * vr[1].y
                           + p[i].z * vr[2].y + p[i].w * vr[3].y;
                acc[i][2] += p[i].x * vr[0].z + p[i].y * vr[1].z
                           + p[i].z * vr[2].z + p[i].w * vr[3].z;
                acc[i][3] += p[i].x * vr[0].w + p[i].y * vr[1].w
                           + p[i].z * vr[2].w + p[i].w * vr[3].w;
            }
        }
    }

    #pragma unroll
    for (int i = 0; i < 4; i++) {
        int r = 4*ty + i;
        float inv = 1.f / l_r[i];
        #pragma unroll
        for (int j = 0; j < 4; j++)
            o[((size_t)b * S_LEN + q0 + r) * D_MODEL + h * DKH + 4*tx + j] =
                acc[i][j] * inv;
    }
}

#define SMEM_ATTN ((2 * BQ * QKPAD + 2 * BQ * VSPAD) * (int)sizeof(float)) // 68096 B

// ---------------------------------------------------------------------------
extern "C" void kernel_launch(void* const* d_in, const int* in_sizes, int n_in,
                              void* d_out, int out_size)
{
    const float* x      = (const float*)d_in[0];
    const float* Wq     = (const float*)d_in[1];
    const float* Wk     = (const float*)d_in[2];
    const float* Wv     = (const float*)d_in[3];
    const float* Wo     = (const float*)d_in[4];
    const float* slopes = (const float*)d_in[5];
    float* out = (float*)d_out;

    float *qkv, *aob;
    __nv_bfloat16 *xa, *aoa, *wqkv, *wo;
    cudaGetSymbolAddress((void**)&qkv,  g_qkv);
    cudaGetSymbolAddress((void**)&aob,  g_ao);
    cudaGetSymbolAddress((void**)&xa,   g_xa);
    cudaGetSymbolAddress((void**)&aoa,  g_aoa);
    cudaGetSymbolAddress((void**)&wqkv, g_wqkv);
    cudaGetSymbolAddress((void**)&wo,   g_wo);

    // smem size + max carveout so multiple CTAs co-reside
    cudaFuncSetAttribute(gemm_mma, cudaFuncAttributeMaxDynamicSharedMemorySize,
                         SMEM_GEMM);
    cudaFuncSetAttribute(gemm_mma, cudaFuncAttributePreferredSharedMemoryCarveout,
                         100);
    cudaFuncSetAttribute(attn_win, cudaFuncAttributeMaxDynamicSharedMemorySize,
                         SMEM_ATTN);
    cudaFuncSetAttribute(attn_win, cudaFuncAttributePreferredSharedMemoryCarveout,
                         100);

    conv_split<<<MROWS, 256>>>(x, xa, 0);
    conv_split_w<<<dim3(D_MODEL, 4), 256>>>(Wq, Wk, Wv, Wo, wqkv, wo);

    gemm_mma<<<dim3(NQKV / GBN, MROWS / GBM), 256, SMEM_GEMM>>>(xa, wqkv, qkv, NQKV);

    attn_win<<<dim3(S_LEN / BQ, NHEADS, BATCH), 256, SMEM_ATTN>>>(
        qkv, qkv + D_MODEL, qkv + 2 * D_MODEL, slopes, aob);

    conv_split<<<MROWS, 256>>>(aob, aoa, 0);

    gemm_mma<<<dim3(D_MODEL / GBN, MROWS / GBM), 256, SMEM_GEMM>>>(aoa, wo, out, D_MODEL);
}